// round 16
// baseline (speedup 1.0000x reference)
#include <cuda_runtime.h>
#include <cuda_bf16.h>
#include <cooperative_groups.h>

namespace cg = cooperative_groups;

// ----------------------------------------------------------------------------
// Problem constants
// ----------------------------------------------------------------------------
#define BATCH 256
#define SEQ 64
#define NG (BATCH*SEQ)          // 16384 graphs
#define NNODES 17
#define NEDGES 81               // 64 edges + 17 self loops
#define HDIM 128                // HEADS*HID = 2*64
#define GROW (NNODES*HDIM)      // 2176 floats per graph
#define MROWS (NG*NNODES)       // 278528 node rows
#define LSTM_IN 2176
#define GATES 512               // 4*128
#define GPG 4                   // graphs per CTA in attention kernels

// ----------------------------------------------------------------------------
// Scratch (device globals). 16B-aligned.
// ----------------------------------------------------------------------------
__device__ __align__(16) float g_bufA[NG * GROW];
__device__ __align__(16) float g_bufB[NG * GROW];
__device__ __align__(16) float g_tmpH[NG * GROW];
__device__ __align__(16) float g_pre [NG * GATES];
__device__ __align__(16) float g_h1  [NG * HDIM];
__device__ __align__(16) float g_h2  [NG * HDIM];

// bf16 hi/lo weight copies (built by prep kernels each launch)
__device__ __align__(16) __nv_bfloat16 g_w0h[GATES * LSTM_IN];
__device__ __align__(16) __nv_bfloat16 g_w0l[GATES * LSTM_IN];
__device__ __align__(16) __nv_bfloat16 g_w1h[GATES * HDIM];
__device__ __align__(16) __nv_bfloat16 g_w1l[GATES * HDIM];
__device__ __align__(16) __nv_bfloat16 g_gwh[3][HDIM * HDIM];   // transposed [N][K]
__device__ __align__(16) __nv_bfloat16 g_gwl[3][HDIM * HDIM];

__device__ __forceinline__ const float* bufsel_r(int s)
{
    switch (s) {
        case 0: return g_bufA;
        case 1: return g_bufB;
        case 2: return g_tmpH;
        case 3: return g_h1;
        default: return g_pre;
    }
}
__device__ __forceinline__ float* bufsel_w(int s)
{
    switch (s) {
        case 0: return g_bufA;
        case 1: return g_bufB;
        case 2: return g_tmpH;
        default: return g_pre;
    }
}
__device__ __forceinline__ void wsel(int s, const __nv_bfloat16** h, const __nv_bfloat16** l)
{
    switch (s) {
        case 0: *h = g_w0h;   *l = g_w0l;   break;
        case 1: *h = g_w1h;   *l = g_w1l;   break;
        case 2: *h = g_gwh[0]; *l = g_gwl[0]; break;
        case 3: *h = g_gwh[1]; *l = g_gwl[1]; break;
        default: *h = g_gwh[2]; *l = g_gwl[2]; break;
    }
}

// ----------------------------------------------------------------------------
// Weight prep: fp32 -> bf16 hi/lo split.
// ----------------------------------------------------------------------------
__device__ __forceinline__ void bf16_split(float x, __nv_bfloat16& h, __nv_bfloat16& l)
{
    h = __float2bfloat16_rn(x);
    l = __float2bfloat16_rn(x - __bfloat162float(h));
}

__global__ void prep_tn(const float* __restrict__ W, int widx, int total)
{
    const __nv_bfloat16 *hc, *lc;
    wsel(widx, &hc, &lc);
    __nv_bfloat16* H = (__nv_bfloat16*)hc;
    __nv_bfloat16* L = (__nv_bfloat16*)lc;
    const int i = blockIdx.x * 256 + threadIdx.x;
    if (i < total) bf16_split(W[i], H[i], L[i]);
}

__global__ void prep_nn_t(const float* __restrict__ W, int widx, int K, int N)
{
    const __nv_bfloat16 *hc, *lc;
    wsel(widx, &hc, &lc);
    __nv_bfloat16* H = (__nv_bfloat16*)hc;
    __nv_bfloat16* L = (__nv_bfloat16*)lc;
    const int i = blockIdx.x * 256 + threadIdx.x;
    if (i < K * N) {
        const int k = i / N, n = i % N;
        bf16_split(W[i], H[n * K + k], L[n * K + k]);
    }
}

// ----------------------------------------------------------------------------
// mma helper
// ----------------------------------------------------------------------------
__device__ __forceinline__ void mma_bf16(float* c, const unsigned* a, unsigned b0, unsigned b1)
{
    asm volatile(
        "mma.sync.aligned.m16n8k16.row.col.f32.bf16.bf16.f32 "
        "{%0,%1,%2,%3}, {%4,%5,%6,%7}, {%8,%9}, {%0,%1,%2,%3};"
        : "+f"(c[0]), "+f"(c[1]), "+f"(c[2]), "+f"(c[3])
        : "r"(a[0]), "r"(a[1]), "r"(a[2]), "r"(a[3]), "r"(b0), "r"(b1));
}

#define BG_STRIDE 40
#define BG_MAT    (128 * BG_STRIDE)

// ----------------------------------------------------------------------------
// Tensor-core GEMM: C = A @ B^T (+biases). Pipelined (R10, proven).
// SWAP=true maps bm to blockIdx.y / bn to blockIdx.x (LSTM pre-gate GEMMs).
// ----------------------------------------------------------------------------
template<bool BIAS, bool SWAP>
__global__ void __launch_bounds__(256)
bgemm(int a_sel, int widx,
      const float* __restrict__ bias1, const float* __restrict__ bias2,
      int out_sel, int M, int Nn, int K)
{
    const float* A = bufsel_r(a_sel);
    float* C = bufsel_w(out_sel);
    const __nv_bfloat16 *Bh_g, *Bl_g;
    wsel(widx, &Bh_g, &Bl_g);

    extern __shared__ __align__(16) __nv_bfloat16 smb[];

    const int tid  = threadIdx.x;
    const int warp = tid >> 5;
    const int lane = tid & 31;
    const int g    = lane >> 2;
    const int tig  = lane & 3;

    const int bm = (SWAP ? blockIdx.y : blockIdx.x) * 128;
    const int bn = (SWAP ? blockIdx.x : blockIdx.y) * 128;
    const int m0 = (warp >> 1) * 32;
    const int n0 = (warp & 1) * 64;

    float acc[2][8][4];
    #pragma unroll
    for (int mt = 0; mt < 2; mt++)
        #pragma unroll
        for (int nt = 0; nt < 8; nt++)
            #pragma unroll
            for (int r = 0; r < 4; r++) acc[mt][nt][r] = 0.f;

    const int ar  = tid >> 1;
    const int akq = (tid & 1) << 4;
    const float* Aptr = A + (long)(bm + ar) * K + akq;
    const __nv_bfloat16* Bhp = Bh_g + (long)(bn + ar) * K + akq;
    const __nv_bfloat16* Blp = Bl_g + (long)(bn + ar) * K + akq;

    const int NT = K >> 5;

    float4 pv[4];
    uint4  pbh[2], pbl[2];

    {
        pv[0] = *(const float4*)(Aptr);
        pv[1] = *(const float4*)(Aptr + 4);
        pv[2] = *(const float4*)(Aptr + 8);
        pv[3] = *(const float4*)(Aptr + 12);
        pbh[0] = *(const uint4*)(Bhp);
        pbh[1] = *(const uint4*)(Bhp + 8);
        pbl[0] = *(const uint4*)(Blp);
        pbl[1] = *(const uint4*)(Blp + 8);
    }
    {
        __nv_bfloat16* Ah = smb;
        __nv_bfloat16* Al = smb + BG_MAT;
        __nv_bfloat16* Bh = smb + 2 * BG_MAT;
        __nv_bfloat16* Bl = smb + 3 * BG_MAT;
        const float vf[16] = { pv[0].x,pv[0].y,pv[0].z,pv[0].w,
                               pv[1].x,pv[1].y,pv[1].z,pv[1].w,
                               pv[2].x,pv[2].y,pv[2].z,pv[2].w,
                               pv[3].x,pv[3].y,pv[3].z,pv[3].w };
        #pragma unroll
        for (int p = 0; p < 8; p++) {
            __nv_bfloat16 h0, l0, h1, l1;
            bf16_split(vf[2*p],     h0, l0);
            bf16_split(vf[2*p + 1], h1, l1);
            __nv_bfloat162 th; th.x = h0; th.y = h1;
            __nv_bfloat162 tl; tl.x = l0; tl.y = l1;
            *(__nv_bfloat162*)&Ah[ar * BG_STRIDE + akq + 2*p] = th;
            *(__nv_bfloat162*)&Al[ar * BG_STRIDE + akq + 2*p] = tl;
        }
        *(uint4*)&Bh[ar * BG_STRIDE + akq]     = pbh[0];
        *(uint4*)&Bh[ar * BG_STRIDE + akq + 8] = pbh[1];
        *(uint4*)&Bl[ar * BG_STRIDE + akq]     = pbl[0];
        *(uint4*)&Bl[ar * BG_STRIDE + akq + 8] = pbl[1];
    }
    __syncthreads();

    int cur = 0;
    for (int kt = 0; kt < NT; kt++) {
        if (kt + 1 < NT) {
            const long ko = (long)(kt + 1) * 32;
            pv[0] = *(const float4*)(Aptr + ko);
            pv[1] = *(const float4*)(Aptr + ko + 4);
            pv[2] = *(const float4*)(Aptr + ko + 8);
            pv[3] = *(const float4*)(Aptr + ko + 12);
            pbh[0] = *(const uint4*)(Bhp + ko);
            pbh[1] = *(const uint4*)(Bhp + ko + 8);
            pbl[0] = *(const uint4*)(Blp + ko);
            pbl[1] = *(const uint4*)(Blp + ko + 8);
        }

        {
            const __nv_bfloat16* Ah = smb + cur * 4 * BG_MAT;
            const __nv_bfloat16* Al = Ah + BG_MAT;
            const __nv_bfloat16* Bh = Ah + 2 * BG_MAT;
            const __nv_bfloat16* Bl = Ah + 3 * BG_MAT;

            #pragma unroll
            for (int kk = 0; kk < 32; kk += 16) {
                unsigned ah[2][4], al[2][4];
                #pragma unroll
                for (int mt = 0; mt < 2; mt++) {
                    const int r = m0 + mt * 16 + g;
                    ah[mt][0] = *(const unsigned*)&Ah[r * BG_STRIDE + kk + 2*tig];
                    ah[mt][1] = *(const unsigned*)&Ah[(r + 8) * BG_STRIDE + kk + 2*tig];
                    ah[mt][2] = *(const unsigned*)&Ah[r * BG_STRIDE + kk + 8 + 2*tig];
                    ah[mt][3] = *(const unsigned*)&Ah[(r + 8) * BG_STRIDE + kk + 8 + 2*tig];
                    al[mt][0] = *(const unsigned*)&Al[r * BG_STRIDE + kk + 2*tig];
                    al[mt][1] = *(const unsigned*)&Al[(r + 8) * BG_STRIDE + kk + 2*tig];
                    al[mt][2] = *(const unsigned*)&Al[r * BG_STRIDE + kk + 8 + 2*tig];
                    al[mt][3] = *(const unsigned*)&Al[(r + 8) * BG_STRIDE + kk + 8 + 2*tig];
                }
                #pragma unroll
                for (int nt = 0; nt < 8; nt++) {
                    const int rn = n0 + nt * 8 + g;
                    const unsigned bh0 = *(const unsigned*)&Bh[rn * BG_STRIDE + kk + 2*tig];
                    const unsigned bh1 = *(const unsigned*)&Bh[rn * BG_STRIDE + kk + 8 + 2*tig];
                    const unsigned bl0 = *(const unsigned*)&Bl[rn * BG_STRIDE + kk + 2*tig];
                    const unsigned bl1 = *(const unsigned*)&Bl[rn * BG_STRIDE + kk + 8 + 2*tig];
                    #pragma unroll
                    for (int mt = 0; mt < 2; mt++) {
                        mma_bf16(acc[mt][nt], ah[mt], bh0, bh1);
                        mma_bf16(acc[mt][nt], ah[mt], bl0, bl1);
                        mma_bf16(acc[mt][nt], al[mt], bh0, bh1);
                    }
                }
            }
        }

        if (kt + 1 < NT) {
            const int nxt = cur ^ 1;
            __nv_bfloat16* Ah = smb + nxt * 4 * BG_MAT;
            __nv_bfloat16* Al = Ah + BG_MAT;
            __nv_bfloat16* Bh = Ah + 2 * BG_MAT;
            __nv_bfloat16* Bl = Ah + 3 * BG_MAT;
            const float vf[16] = { pv[0].x,pv[0].y,pv[0].z,pv[0].w,
                                   pv[1].x,pv[1].y,pv[1].z,pv[1].w,
                                   pv[2].x,pv[2].y,pv[2].z,pv[2].w,
                                   pv[3].x,pv[3].y,pv[3].z,pv[3].w };
            #pragma unroll
            for (int p = 0; p < 8; p++) {
                __nv_bfloat16 h0, l0, h1, l1;
                bf16_split(vf[2*p],     h0, l0);
                bf16_split(vf[2*p + 1], h1, l1);
                __nv_bfloat162 th; th.x = h0; th.y = h1;
                __nv_bfloat162 tl; tl.x = l0; tl.y = l1;
                *(__nv_bfloat162*)&Ah[ar * BG_STRIDE + akq + 2*p] = th;
                *(__nv_bfloat162*)&Al[ar * BG_STRIDE + akq + 2*p] = tl;
            }
            *(uint4*)&Bh[ar * BG_STRIDE + akq]     = pbh[0];
            *(uint4*)&Bh[ar * BG_STRIDE + akq + 8] = pbh[1];
            *(uint4*)&Bl[ar * BG_STRIDE + akq]     = pbl[0];
            *(uint4*)&Bl[ar * BG_STRIDE + akq + 8] = pbl[1];
            __syncthreads();
            cur = nxt;
        }
    }

    #pragma unroll
    for (int mt = 0; mt < 2; mt++) {
        const long row = bm + m0 + mt * 16 + g;
        #pragma unroll
        for (int nt = 0; nt < 8; nt++) {
            const int col = bn + n0 + nt * 8 + 2 * tig;
            float c0 = acc[mt][nt][0], c1 = acc[mt][nt][1];
            float c2 = acc[mt][nt][2], c3 = acc[mt][nt][3];
            if (BIAS) {
                const float b0 = bias1[col]     + bias2[col];
                const float b1 = bias1[col + 1] + bias2[col + 1];
                c0 += b0; c1 += b1; c2 += b0; c3 += b1;
            }
            *(float2*)&C[row * Nn + col]       = make_float2(c0, c1);
            *(float2*)&C[(row + 8) * Nn + col] = make_float2(c2, c3);
        }
    }
}

// ----------------------------------------------------------------------------
// Shared attention phases, GPG graphs per CTA (R3-proven structure; GPG=4
// halves smem vs R3's 8 -> ~5 CTAs/SM instead of 2 for latency hiding).
// ----------------------------------------------------------------------------
__device__ __forceinline__ void gat_attn_body(
    float* sH, const float* sAs, const float* sAd, const float* sB,
    float* s_as, float* s_ad, float* s_m, float* s_dn, float* s_ev,
    const int* s_src, const int* s_dst, const int* s_cs, const int* s_ce,
    float* outb, long out_base_graph, int relu_flag)
{
    const int tid = threadIdx.x;

    for (int i = tid; i < GPG * 64; i += 256) {
        const int g = i >> 6, t = i & 63;
        if (t < 34) {
            const int n = t >> 1, hh = t & 1;
            const float* hp = &sH[g * GROW + n * 128 + hh * 64];
            float as = 0.f, ad = 0.f;
            #pragma unroll 8
            for (int d = 0; d < 64; d++) {
                as += hp[d] * sAs[hh * 64 + d];
                ad += hp[d] * sAd[hh * 64 + d];
            }
            s_as[g * 34 + t] = as; s_ad[g * 34 + t] = ad;
        }
    }
    __syncthreads();

    for (int i = tid; i < GPG * 256; i += 256) {
        const int g = i >> 8, t = i & 255;
        if (t < 162) {
            const int e = t >> 1, hh = t & 1;
            const float raw = s_as[g * 34 + s_src[e] * 2 + hh]
                            + s_ad[g * 34 + s_dst[e] * 2 + hh];
            s_ev[g * 162 + t] = raw > 0.f ? raw : 0.2f * raw;
        }
    }
    __syncthreads();

    for (int i = tid; i < GPG * 64; i += 256) {
        const int g = i >> 6, t = i & 63;
        if (t < 34) {
            const int n = t >> 1, hh = t & 1;
            float m = -1e30f;
            for (int p = s_cs[n]; p < s_cs[n + 1]; p++)
                m = fmaxf(m, s_ev[g * 162 + s_ce[p] * 2 + hh]);
            float den = 0.f;
            for (int p = s_cs[n]; p < s_cs[n + 1]; p++)
                den += __expf(s_ev[g * 162 + s_ce[p] * 2 + hh] - m);
            s_m[g * 34 + t] = m; s_dn[g * 34 + t] = den;
        }
    }
    __syncthreads();

    for (int i = tid; i < GPG * 256; i += 256) {
        const int g = i >> 8, t = i & 255;
        if (t < 162) {
            const int e = t >> 1, hh = t & 1;
            const int d = s_dst[e];
            s_ev[g * 162 + t] = __expf(s_ev[g * 162 + t] - s_m[g * 34 + d * 2 + hh])
                                / (s_dn[g * 34 + d * 2 + hh] + 1e-16f);
        }
    }
    __syncthreads();

    for (int i = tid; i < GPG * NNODES * 32; i += 256) {
        const int g = i / (NNODES * 32);
        const int r = i - g * (NNODES * 32);
        const int n = r >> 5;
        const int q = (r & 31) << 2;
        const int hh = q >> 6;
        float4 acc = make_float4(0.f, 0.f, 0.f, 0.f);
        for (int p = s_cs[n]; p < s_cs[n + 1]; p++) {
            const int e = s_ce[p];
            const float al = s_ev[g * 162 + e * 2 + hh];
            const float4 hv = *(const float4*)&sH[g * GROW + s_src[e] * 128 + q];
            acc.x += al * hv.x; acc.y += al * hv.y;
            acc.z += al * hv.z; acc.w += al * hv.w;
        }
        const float4 b4 = *(const float4*)&sB[q];
        acc.x += b4.x; acc.y += b4.y; acc.z += b4.z; acc.w += b4.w;
        if (relu_flag) {
            acc.x = fmaxf(acc.x, 0.f); acc.y = fmaxf(acc.y, 0.f);
            acc.z = fmaxf(acc.z, 0.f); acc.w = fmaxf(acc.w, 0.f);
        }
        *(float4*)&outb[(out_base_graph + g) * GROW + n * 128 + q] = acc;
    }
}

__device__ __forceinline__ void gat_build_csr(
    const int* __restrict__ edge_index,
    int* s_src, int* s_dst, int* s_cs, int* s_ce)
{
    int cnt[NNODES];
    for (int n = 0; n < NNODES; n++) cnt[n] = 0;
    for (int e = 0; e < NEDGES; e++) {
        int s = (e < 64) ? edge_index[e]      : (e - 64);
        int d = (e < 64) ? edge_index[64 + e] : (e - 64);
        s_src[e] = s; s_dst[e] = d; cnt[d]++;
    }
    int off = 0;
    for (int n = 0; n < NNODES; n++) { s_cs[n] = off; off += cnt[n]; cnt[n] = s_cs[n]; }
    s_cs[NNODES] = off;
    for (int e = 0; e < NEDGES; e++) s_ce[cnt[s_dst[e]]++] = e;
}

// ----------------------------------------------------------------------------
// GAT layer 0, fused projection (CIN=3): H computed in smem directly from x.
// ----------------------------------------------------------------------------
__global__ void __launch_bounds__(256)
gat_attn0(const float* __restrict__ x, const float* __restrict__ W0,
          const float* __restrict__ a_src, const float* __restrict__ a_dst,
          const float* __restrict__ bias, const int* __restrict__ edge_index,
          int out_sel, int relu_flag)
{
    extern __shared__ __align__(16) float smem[];
    float* sH   = smem;                    // GPG*2176
    float* sW0  = sH  + GPG * GROW;        // 384
    float* sX   = sW0 + 384;               // GPG*17*3
    float* sAs  = sX  + GPG * NNODES * 3 + 1;  // +1 pad (keep 4-align below)
    // re-align to 4 floats
    sAs = (float*)(((unsigned long)(sX + GPG * NNODES * 3) + 15) & ~15UL);
    float* sAd  = sAs + 128;
    float* sB   = sAd + 128;
    float* s_as = sB  + 128;               // GPG*34
    float* s_ad = s_as + GPG * 34;
    float* s_m  = s_ad + GPG * 34;
    float* s_dn = s_m  + GPG * 34;
    float* s_ev = s_dn + GPG * 34;         // GPG*162
    int*   s_src = (int*)(s_ev + GPG * 162);
    int*   s_dst = s_src + NEDGES;
    int*   s_cs  = s_dst + NEDGES;
    int*   s_ce  = s_cs + NNODES + 1;

    const int tid = threadIdx.x;

    if (tid == 0) gat_build_csr(edge_index, s_src, s_dst, s_cs, s_ce);
    if (tid < 128) { sAs[tid] = a_src[tid]; sAd[tid] = a_dst[tid]; sB[tid] = bias[tid]; }
    for (int i = tid; i < 384; i += 256) sW0[i] = W0[i];
    const float* xg = x + (long)blockIdx.x * (GPG * NNODES * 3);
    for (int i = tid; i < GPG * NNODES * 3; i += 256) sX[i] = xg[i];
    __syncthreads();

    for (int i = tid; i < GPG * NNODES * 32; i += 256) {
        const int g = i / (NNODES * 32);
        const int r = i - g * (NNODES * 32);
        const int n = r >> 5;
        const int q = (r & 31) << 2;
        const float* xp = &sX[(g * NNODES + n) * 3];
        const float x0 = xp[0], x1 = xp[1], x2 = xp[2];
        const float4 w0 = *(const float4*)&sW0[0 * 128 + q];
        const float4 w1 = *(const float4*)&sW0[1 * 128 + q];
        const float4 w2 = *(const float4*)&sW0[2 * 128 + q];
        float4 o;
        o.x = x0 * w0.x + x1 * w1.x + x2 * w2.x;
        o.y = x0 * w0.y + x1 * w1.y + x2 * w2.y;
        o.z = x0 * w0.z + x1 * w1.z + x2 * w2.z;
        o.w = x0 * w0.w + x1 * w1.w + x2 * w2.w;
        *(float4*)&sH[g * GROW + n * 128 + q] = o;
    }
    __syncthreads();

    gat_attn_body(sH, sAs, sAd, sB, s_as, s_ad, s_m, s_dn, s_ev,
                  s_src, s_dst, s_cs, s_ce,
                  bufsel_w(out_sel), (long)blockIdx.x * GPG, relu_flag);
}

// ----------------------------------------------------------------------------
// GAT attention for layers 1-3 (reads packed g_tmpH). R3-proven phases.
// ----------------------------------------------------------------------------
__global__ void __launch_bounds__(256)
gat_attn(const float* __restrict__ a_src, const float* __restrict__ a_dst,
         const float* __restrict__ bias, const int* __restrict__ edge_index,
         int out_sel, int relu_flag)
{
    extern __shared__ __align__(16) float smem[];
    float* sH   = smem;                    // GPG*2176
    float* sAs  = sH  + GPG * GROW;
    float* sAd  = sAs + 128;
    float* sB   = sAd + 128;
    float* s_as = sB  + 128;
    float* s_ad = s_as + GPG * 34;
    float* s_m  = s_ad + GPG * 34;
    float* s_dn = s_m  + GPG * 34;
    float* s_ev = s_dn + GPG * 34;
    int*   s_src = (int*)(s_ev + GPG * 162);
    int*   s_dst = s_src + NEDGES;
    int*   s_cs  = s_dst + NEDGES;
    int*   s_ce  = s_cs + NNODES + 1;

    const int tid = threadIdx.x;

    if (tid == 0) gat_build_csr(edge_index, s_src, s_dst, s_cs, s_ce);
    if (tid < 128) { sAs[tid] = a_src[tid]; sAd[tid] = a_dst[tid]; sB[tid] = bias[tid]; }

    const float* Hsrc = g_tmpH + (long)blockIdx.x * (GPG * GROW);
    for (int i = tid; i < (GPG * GROW) / 4; i += 256)
        *(float4*)&sH[i * 4] = *(const float4*)&Hsrc[i * 4];
    __syncthreads();

    gat_attn_body(sH, sAs, sAd, sB, s_as, s_ad, s_m, s_dn, s_ev,
                  s_src, s_dst, s_cs, s_ce,
                  bufsel_w(out_sel), (long)blockIdx.x * GPG, relu_flag);
}

// ----------------------------------------------------------------------------
// LSTM recurrence: 32 clusters x 4 CTAs (grid (32,4), cluster (1,4)).
// h exchanged via DSMEM; one cluster.sync per step (double-buffered sOut).
// ----------------------------------------------------------------------------
__global__ void __cluster_dims__(1, 4, 1) lstm_recur(const float* __restrict__ whh, int out_sel)
{
    extern __shared__ __align__(16) float smem[];
    float* sW   = smem;                 // 128*132
    float* sH   = sW + 128 * 132;       // 8*128
    float* sC   = sH + 8 * 128;         // 8*32
    float* sPre = sC + 8 * 32;          // 8*128
    float* sOut = sPre + 8 * 128;       // 2 * 8*32

    float* hseq = (out_sel == 0) ? g_h1 : g_h2;
    const float* pre = g_pre;

    cg::cluster_group cluster = cg::this_cluster();

    const int tid = threadIdx.x;
    const int b0 = blockIdx.x * 8;
    const int myrank = blockIdx.y;
    const int d0 = myrank * 32;

    const int j    = tid & 127;
    const int half = tid >> 7;
    const int gidx = ((j >> 5) << 7) + d0 + (j & 31);

    float* peerOut[4];
    #pragma unroll
    for (int r = 0; r < 4; r++)
        peerOut[r] = cluster.map_shared_rank(sOut, r);

    for (int i = tid; i < 128 * 128; i += blockDim.x) {
        const int r = i >> 7, k = i & 127;
        const int jr = ((r >> 5) << 7) + d0 + (r & 31);
        sW[r * 132 + k] = whh[jr * 128 + k];
    }
    for (int i = tid; i < 8 * 128; i += blockDim.x) sH[i] = 0.f;
    {
        const int row = tid >> 5, l = tid & 31;
        sC[row * 32 + l] = 0.f;
    }
    __syncthreads();
    cluster.sync();

    int parity = 0;
    for (int t = 0; t < SEQ; t++) {
        {
            const long pb = ((long)(b0 + half * 4) * SEQ + t) * GATES + gidx;
            const long rs = (long)SEQ * GATES;
            float a0 = pre[pb];
            float a1 = pre[pb + rs];
            float a2 = pre[pb + 2 * rs];
            float a3 = pre[pb + 3 * rs];
            const float4* w4 = (const float4*)&sW[j * 132];
            const float4* h0 = (const float4*)&sH[(half * 4 + 0) * 128];
            const float4* h1 = (const float4*)&sH[(half * 4 + 1) * 128];
            const float4* h2 = (const float4*)&sH[(half * 4 + 2) * 128];
            const float4* h3 = (const float4*)&sH[(half * 4 + 3) * 128];
            #pragma unroll 8
            for (int k4 = 0; k4 < 32; k4++) {
                const float4 w = w4[k4];
                const float4 v0 = h0[k4];
                const float4 v1 = h1[k4];
                const float4 v2 = h2[k4];
                const float4 v3 = h3[k4];
                a0 += w.x * v0.x + w.y * v0.y + w.z * v0.z + w.w * v0.w;
                a1 += w.x * v1.x + w.y * v1.y + w.z * v1.z + w.w * v1.w;
                a2 += w.x * v2.x + w.y * v2.y + w.z * v2.z + w.w * v2.w;
                a3 += w.x * v3.x + w.y * v3.y + w.z * v3.z + w.w * v3.w;
            }
            sPre[(half * 4 + 0) * 128 + j] = a0;
            sPre[(half * 4 + 1) * 128 + j] = a1;
            sPre[(half * 4 + 2) * 128 + j] = a2;
            sPre[(half * 4 + 3) * 128 + j] = a3;
        }
        __syncthreads();

        {
            const int row = tid >> 5, l = tid & 31;
            const float a0 = sPre[row * 128 + l];
            const float a1 = sPre[row * 128 + 32 + l];
            const float a2 = sPre[row * 128 + 64 + l];
            const float a3 = sPre[row * 128 + 96 + l];
            const float ig = 1.f / (1.f + expf(-a0));
            const float fg = 1.f / (1.f + expf(-a1));
            const float gg = tanhf(a2);
            const float og = 1.f / (1.f + expf(-a3));
            const float c = fg * sC[row * 32 + l] + ig * gg;
            sC[row * 32 + l] = c;
            const float h = og * tanhf(c);
            sOut[parity * 256 + row * 32 + l] = h;
            hseq[((long)(b0 + row) * SEQ + t) * 128 + d0 + l] = h;
        }

        cluster.sync();
        for (int i = tid; i < 8 * 128; i += blockDim.x) {
            const int row = i >> 7, k = i & 127;
            const int srck = k >> 5, l = k & 31;
            sH[i] = peerOut[srck][parity * 256 + row * 32 + l];
        }
        __syncthreads();
        parity ^= 1;
    }
}

// ----------------------------------------------------------------------------
// Temporal attention + FC head. One CTA (128 threads) per batch row.
// ----------------------------------------------------------------------------
__global__ void attn_fc(const float* __restrict__ attn_w, const float* __restrict__ attn_b,
                        const float* __restrict__ fc_w,   const float* __restrict__ fc_b,
                        float* __restrict__ out)
{
    __shared__ float sw[128];
    __shared__ float sc[SEQ];
    __shared__ float sctx[128];

    const int b = blockIdx.x, tid = threadIdx.x;
    const float* h2 = g_h2 + (long)b * SEQ * 128;

    sw[tid] = attn_w[tid];
    __syncthreads();

    if (tid < SEQ) {
        const float* hp = h2 + tid * 128;
        float acc = attn_b[0];
        #pragma unroll 8
        for (int k = 0; k < 128; k++) acc += hp[k] * sw[k];
        sc[tid] = tanhf(acc);
    }
    __syncthreads();

    if (tid == 0) {
        float m = -1e30f;
        for (int t = 0; t < SEQ; t++) m = fmaxf(m, sc[t]);
        float s = 0.f;
        for (int t = 0; t < SEQ; t++) { sc[t] = __expf(sc[t] - m); s += sc[t]; }
        const float inv = 1.f / s;
        for (int t = 0; t < SEQ; t++) sc[t] *= inv;
    }
    __syncthreads();

    {
        float acc = 0.f;
        for (int t = 0; t < SEQ; t++) acc += sc[t] * h2[t * 128 + tid];
        sctx[tid] = acc;
    }
    __syncthreads();

    if (tid < 10) {
        float acc = fc_b[tid];
        #pragma unroll 8
        for (int k = 0; k < 128; k++) acc += sctx[k] * fc_w[tid * 128 + k];
        out[b * 10 + tid] = acc;
    }
}

// ----------------------------------------------------------------------------
// Launcher
// ----------------------------------------------------------------------------
extern "C" void kernel_launch(void* const* d_in, const int* in_sizes, int n_in,
                              void* d_out, int out_size)
{
    const float* x    = (const float*)d_in[0];
    const int*   eidx = (const int*)  d_in[1];
    const float* gw[4]  = { (const float*)d_in[2],  (const float*)d_in[6],
                            (const float*)d_in[10], (const float*)d_in[14] };
    const float* gas[4] = { (const float*)d_in[3],  (const float*)d_in[7],
                            (const float*)d_in[11], (const float*)d_in[15] };
    const float* gad[4] = { (const float*)d_in[4],  (const float*)d_in[8],
                            (const float*)d_in[12], (const float*)d_in[16] };
    const float* gb[4]  = { (const float*)d_in[5],  (const float*)d_in[9],
                            (const float*)d_in[13], (const float*)d_in[17] };
    const float* wih0 = (const float*)d_in[18];
    const float* whh0 = (const float*)d_in[19];
    const float* bih0 = (const float*)d_in[20];
    const float* bhh0 = (const float*)d_in[21];
    const float* wih1 = (const float*)d_in[22];
    const float* whh1 = (const float*)d_in[23];
    const float* bih1 = (const float*)d_in[24];
    const float* bhh1 = (const float*)d_in[25];
    const float* attn_w = (const float*)d_in[26];
    const float* attn_b = (const float*)d_in[27];
    const float* fc_w   = (const float*)d_in[28];
    const float* fc_b   = (const float*)d_in[29];
    float* out = (float*)d_out;

    const int smem_attn  = ((GPG * GROW + 3 * 128 + 4 * (GPG * 34) + GPG * 162) +
                            (NEDGES * 3 + NNODES + 1 + 8)) * 4;
    const int smem_attn0 = smem_attn + (384 + GPG * NNODES * 3 + 8) * 4;
    const int smem_rec   = (128 * 132 + 8 * 128 + 8 * 32 + 8 * 128 + 2 * 8 * 32) * 4;
    const int smem_bg    = 2 * 4 * BG_MAT * 2;   // 81920

    cudaFuncSetAttribute((const void*)gat_attn,
                         cudaFuncAttributeMaxDynamicSharedMemorySize, smem_attn);
    cudaFuncSetAttribute((const void*)gat_attn0,
                         cudaFuncAttributeMaxDynamicSharedMemorySize, smem_attn0);
    cudaFuncSetAttribute((const void*)lstm_recur,
                         cudaFuncAttributeMaxDynamicSharedMemorySize, smem_rec);
    cudaFuncSetAttribute((const void*)bgemm<false, false>,
                         cudaFuncAttributeMaxDynamicSharedMemorySize, smem_bg);
    cudaFuncSetAttribute((const void*)bgemm<true, true>,
                         cudaFuncAttributeMaxDynamicSharedMemorySize, smem_bg);

    const int attn_grid = NG / GPG;      // 4096
    const int mm_grid   = MROWS / 128;   // 2176

    // weight prep (bf16 hi/lo)
    prep_tn  <<<(GATES * LSTM_IN + 255) / 256, 256>>>(wih0, 0, GATES * LSTM_IN);
    prep_tn  <<<(GATES * HDIM    + 255) / 256, 256>>>(wih1, 1, GATES * HDIM);
    prep_nn_t<<<(HDIM * HDIM     + 255) / 256, 256>>>(gw[1], 2, HDIM, HDIM);
    prep_nn_t<<<(HDIM * HDIM     + 255) / 256, 256>>>(gw[2], 3, HDIM, HDIM);
    prep_nn_t<<<(HDIM * HDIM     + 255) / 256, 256>>>(gw[3], 4, HDIM, HDIM);

    // ---- GAT layer 0 (fused projection): x -> bufA (relu)
    gat_attn0<<<attn_grid, 256, smem_attn0>>>(x, gw[0], gas[0], gad[0], gb[0], eidx, 0, 1);

    // ---- GAT layer 1: bufA @ W1 -> tmpH -> attn -> bufB
    bgemm<false, false><<<dim3(mm_grid, 1), 256, smem_bg>>>(0, 2, nullptr, nullptr, 2, MROWS, 128, 128);
    gat_attn<<<attn_grid, 256, smem_attn>>>(gas[1], gad[1], gb[1], eidx, 1, 0);

    // ---- GAT layer 2: bufB @ W2 -> tmpH -> attn -> bufA (relu)
    bgemm<false, false><<<dim3(mm_grid, 1), 256, smem_bg>>>(1, 3, nullptr, nullptr, 2, MROWS, 128, 128);
    gat_attn<<<attn_grid, 256, smem_attn>>>(gas[2], gad[2], gb[2], eidx, 0, 1);

    // ---- GAT layer 3: bufA @ W3 -> tmpH -> attn -> bufB
    bgemm<false, false><<<dim3(mm_grid, 1), 256, smem_bg>>>(0, 4, nullptr, nullptr, 2, MROWS, 128, 128);
    gat_attn<<<attn_grid, 256, smem_attn>>>(gas[3], gad[3], gb[3], eidx, 1, 0);

    // ---- LSTM layer 0: pre-gates GEMM (SWAP grid) + recurrence
    bgemm<true, true><<<dim3(GATES / 128, NG / 128), 256, smem_bg>>>(1, 0, bih0, bhh0, 4, NG, GATES, LSTM_IN);
    lstm_recur<<<dim3(32, 4), 256, smem_rec>>>(whh0, 0);

    // ---- LSTM layer 1: pre-gates GEMM (SWAP grid) + recurrence
    bgemm<true, true><<<dim3(GATES / 128, NG / 128), 256, smem_bg>>>(3, 1, bih1, bhh1, 4, NG, GATES, HDIM);
    lstm_recur<<<dim3(32, 4), 256, smem_rec>>>(whh1, 1);

    // ---- head
    attn_fc<<<BATCH, 128>>>(attn_w, attn_b, fc_w, fc_b, out);
}

// round 17
// speedup vs baseline: 1.1751x; 1.1751x over previous
#include <cuda_runtime.h>
#include <cuda_bf16.h>
#include <cooperative_groups.h>

namespace cg = cooperative_groups;

// ----------------------------------------------------------------------------
// Problem constants
// ----------------------------------------------------------------------------
#define BATCH 256
#define SEQ 64
#define NG (BATCH*SEQ)          // 16384 graphs
#define NNODES 17
#define NEDGES 81               // 64 edges + 17 self loops
#define HDIM 128                // HEADS*HID = 2*64
#define GROW (NNODES*HDIM)      // 2176 floats per graph
#define MROWS (NG*NNODES)       // 278528 node rows
#define LSTM_IN 2176
#define GATES 512               // 4*128
#define GPG 4                   // graphs per CTA in attention kernels

// ----------------------------------------------------------------------------
// Scratch (device globals). 16B-aligned.
// ----------------------------------------------------------------------------
__device__ __align__(16) float g_bufA[NG * GROW];
__device__ __align__(16) float g_bufB[NG * GROW];
__device__ __align__(16) float g_tmpH[NG * GROW];
__device__ __align__(16) float g_pre [NG * GATES];
__device__ __align__(16) float g_h1  [NG * HDIM];
__device__ __align__(16) float g_h2  [NG * HDIM];

// CSR for the (shared) graph topology, built once per launch by prep_csr
__device__ int g_csr_src[NEDGES];
__device__ int g_csr_dst[NEDGES];
__device__ int g_csr_cs [NNODES + 1];
__device__ int g_csr_ce [NEDGES];

// bf16 hi/lo weight copies (built by prep kernels each launch)
__device__ __align__(16) __nv_bfloat16 g_w0h[GATES * LSTM_IN];
__device__ __align__(16) __nv_bfloat16 g_w0l[GATES * LSTM_IN];
__device__ __align__(16) __nv_bfloat16 g_w1h[GATES * HDIM];
__device__ __align__(16) __nv_bfloat16 g_w1l[GATES * HDIM];
__device__ __align__(16) __nv_bfloat16 g_gwh[3][HDIM * HDIM];   // transposed [N][K]
__device__ __align__(16) __nv_bfloat16 g_gwl[3][HDIM * HDIM];

__device__ __forceinline__ const float* bufsel_r(int s)
{
    switch (s) {
        case 0: return g_bufA;
        case 1: return g_bufB;
        case 2: return g_tmpH;
        case 3: return g_h1;
        default: return g_pre;
    }
}
__device__ __forceinline__ float* bufsel_w(int s)
{
    switch (s) {
        case 0: return g_bufA;
        case 1: return g_bufB;
        case 2: return g_tmpH;
        default: return g_pre;
    }
}
__device__ __forceinline__ void wsel(int s, const __nv_bfloat16** h, const __nv_bfloat16** l)
{
    switch (s) {
        case 0: *h = g_w0h;   *l = g_w0l;   break;
        case 1: *h = g_w1h;   *l = g_w1l;   break;
        case 2: *h = g_gwh[0]; *l = g_gwl[0]; break;
        case 3: *h = g_gwh[1]; *l = g_gwl[1]; break;
        default: *h = g_gwh[2]; *l = g_gwl[2]; break;
    }
}

// ----------------------------------------------------------------------------
// CSR prep: build once (in smem, serial tid0), dump to device globals.
// ----------------------------------------------------------------------------
__global__ void prep_csr(const int* __restrict__ edge_index)
{
    __shared__ int s_src[NEDGES], s_dst[NEDGES], s_cs[NNODES + 1], s_ce[NEDGES];
    const int tid = threadIdx.x;
    if (tid == 0) {
        int cnt[NNODES];
        for (int n = 0; n < NNODES; n++) cnt[n] = 0;
        for (int e = 0; e < NEDGES; e++) {
            int s = (e < 64) ? edge_index[e]      : (e - 64);
            int d = (e < 64) ? edge_index[64 + e] : (e - 64);
            s_src[e] = s; s_dst[e] = d; cnt[d]++;
        }
        int off = 0;
        for (int n = 0; n < NNODES; n++) { s_cs[n] = off; off += cnt[n]; cnt[n] = s_cs[n]; }
        s_cs[NNODES] = off;
        for (int e = 0; e < NEDGES; e++) s_ce[cnt[s_dst[e]]++] = e;
    }
    __syncthreads();
    if (tid < NEDGES) {
        g_csr_src[tid] = s_src[tid];
        g_csr_dst[tid] = s_dst[tid];
        g_csr_ce[tid]  = s_ce[tid];
    }
    if (tid < NNODES + 1) g_csr_cs[tid] = s_cs[tid];
}

// ----------------------------------------------------------------------------
// Weight prep: fp32 -> bf16 hi/lo split.
// ----------------------------------------------------------------------------
__device__ __forceinline__ void bf16_split(float x, __nv_bfloat16& h, __nv_bfloat16& l)
{
    h = __float2bfloat16_rn(x);
    l = __float2bfloat16_rn(x - __bfloat162float(h));
}

__global__ void prep_tn(const float* __restrict__ W, int widx, int total)
{
    const __nv_bfloat16 *hc, *lc;
    wsel(widx, &hc, &lc);
    __nv_bfloat16* H = (__nv_bfloat16*)hc;
    __nv_bfloat16* L = (__nv_bfloat16*)lc;
    const int i = blockIdx.x * 256 + threadIdx.x;
    if (i < total) bf16_split(W[i], H[i], L[i]);
}

__global__ void prep_nn_t(const float* __restrict__ W, int widx, int K, int N)
{
    const __nv_bfloat16 *hc, *lc;
    wsel(widx, &hc, &lc);
    __nv_bfloat16* H = (__nv_bfloat16*)hc;
    __nv_bfloat16* L = (__nv_bfloat16*)lc;
    const int i = blockIdx.x * 256 + threadIdx.x;
    if (i < K * N) {
        const int k = i / N, n = i % N;
        bf16_split(W[i], H[n * K + k], L[n * K + k]);
    }
}

// ----------------------------------------------------------------------------
// mma helper
// ----------------------------------------------------------------------------
__device__ __forceinline__ void mma_bf16(float* c, const unsigned* a, unsigned b0, unsigned b1)
{
    asm volatile(
        "mma.sync.aligned.m16n8k16.row.col.f32.bf16.bf16.f32 "
        "{%0,%1,%2,%3}, {%4,%5,%6,%7}, {%8,%9}, {%0,%1,%2,%3};"
        : "+f"(c[0]), "+f"(c[1]), "+f"(c[2]), "+f"(c[3])
        : "r"(a[0]), "r"(a[1]), "r"(a[2]), "r"(a[3]), "r"(b0), "r"(b1));
}

#define BG_STRIDE 40
#define BG_MAT    (128 * BG_STRIDE)

// ----------------------------------------------------------------------------
// Tensor-core GEMM: C = A @ B^T (+biases). Pipelined (R10, proven).
// SWAP=true maps bm to blockIdx.y / bn to blockIdx.x (LSTM pre-gate GEMMs).
// ----------------------------------------------------------------------------
template<bool BIAS, bool SWAP>
__global__ void __launch_bounds__(256)
bgemm(int a_sel, int widx,
      const float* __restrict__ bias1, const float* __restrict__ bias2,
      int out_sel, int M, int Nn, int K)
{
    const float* A = bufsel_r(a_sel);
    float* C = bufsel_w(out_sel);
    const __nv_bfloat16 *Bh_g, *Bl_g;
    wsel(widx, &Bh_g, &Bl_g);

    extern __shared__ __align__(16) __nv_bfloat16 smb[];

    const int tid  = threadIdx.x;
    const int warp = tid >> 5;
    const int lane = tid & 31;
    const int g    = lane >> 2;
    const int tig  = lane & 3;

    const int bm = (SWAP ? blockIdx.y : blockIdx.x) * 128;
    const int bn = (SWAP ? blockIdx.x : blockIdx.y) * 128;
    const int m0 = (warp >> 1) * 32;
    const int n0 = (warp & 1) * 64;

    float acc[2][8][4];
    #pragma unroll
    for (int mt = 0; mt < 2; mt++)
        #pragma unroll
        for (int nt = 0; nt < 8; nt++)
            #pragma unroll
            for (int r = 0; r < 4; r++) acc[mt][nt][r] = 0.f;

    const int ar  = tid >> 1;
    const int akq = (tid & 1) << 4;
    const float* Aptr = A + (long)(bm + ar) * K + akq;
    const __nv_bfloat16* Bhp = Bh_g + (long)(bn + ar) * K + akq;
    const __nv_bfloat16* Blp = Bl_g + (long)(bn + ar) * K + akq;

    const int NT = K >> 5;

    float4 pv[4];
    uint4  pbh[2], pbl[2];

    {
        pv[0] = *(const float4*)(Aptr);
        pv[1] = *(const float4*)(Aptr + 4);
        pv[2] = *(const float4*)(Aptr + 8);
        pv[3] = *(const float4*)(Aptr + 12);
        pbh[0] = *(const uint4*)(Bhp);
        pbh[1] = *(const uint4*)(Bhp + 8);
        pbl[0] = *(const uint4*)(Blp);
        pbl[1] = *(const uint4*)(Blp + 8);
    }
    {
        __nv_bfloat16* Ah = smb;
        __nv_bfloat16* Al = smb + BG_MAT;
        __nv_bfloat16* Bh = smb + 2 * BG_MAT;
        __nv_bfloat16* Bl = smb + 3 * BG_MAT;
        const float vf[16] = { pv[0].x,pv[0].y,pv[0].z,pv[0].w,
                               pv[1].x,pv[1].y,pv[1].z,pv[1].w,
                               pv[2].x,pv[2].y,pv[2].z,pv[2].w,
                               pv[3].x,pv[3].y,pv[3].z,pv[3].w };
        #pragma unroll
        for (int p = 0; p < 8; p++) {
            __nv_bfloat16 h0, l0, h1, l1;
            bf16_split(vf[2*p],     h0, l0);
            bf16_split(vf[2*p + 1], h1, l1);
            __nv_bfloat162 th; th.x = h0; th.y = h1;
            __nv_bfloat162 tl; tl.x = l0; tl.y = l1;
            *(__nv_bfloat162*)&Ah[ar * BG_STRIDE + akq + 2*p] = th;
            *(__nv_bfloat162*)&Al[ar * BG_STRIDE + akq + 2*p] = tl;
        }
        *(uint4*)&Bh[ar * BG_STRIDE + akq]     = pbh[0];
        *(uint4*)&Bh[ar * BG_STRIDE + akq + 8] = pbh[1];
        *(uint4*)&Bl[ar * BG_STRIDE + akq]     = pbl[0];
        *(uint4*)&Bl[ar * BG_STRIDE + akq + 8] = pbl[1];
    }
    __syncthreads();

    int cur = 0;
    for (int kt = 0; kt < NT; kt++) {
        if (kt + 1 < NT) {
            const long ko = (long)(kt + 1) * 32;
            pv[0] = *(const float4*)(Aptr + ko);
            pv[1] = *(const float4*)(Aptr + ko + 4);
            pv[2] = *(const float4*)(Aptr + ko + 8);
            pv[3] = *(const float4*)(Aptr + ko + 12);
            pbh[0] = *(const uint4*)(Bhp + ko);
            pbh[1] = *(const uint4*)(Bhp + ko + 8);
            pbl[0] = *(const uint4*)(Blp + ko);
            pbl[1] = *(const uint4*)(Blp + ko + 8);
        }

        {
            const __nv_bfloat16* Ah = smb + cur * 4 * BG_MAT;
            const __nv_bfloat16* Al = Ah + BG_MAT;
            const __nv_bfloat16* Bh = Ah + 2 * BG_MAT;
            const __nv_bfloat16* Bl = Ah + 3 * BG_MAT;

            #pragma unroll
            for (int kk = 0; kk < 32; kk += 16) {
                unsigned ah[2][4], al[2][4];
                #pragma unroll
                for (int mt = 0; mt < 2; mt++) {
                    const int r = m0 + mt * 16 + g;
                    ah[mt][0] = *(const unsigned*)&Ah[r * BG_STRIDE + kk + 2*tig];
                    ah[mt][1] = *(const unsigned*)&Ah[(r + 8) * BG_STRIDE + kk + 2*tig];
                    ah[mt][2] = *(const unsigned*)&Ah[r * BG_STRIDE + kk + 8 + 2*tig];
                    ah[mt][3] = *(const unsigned*)&Ah[(r + 8) * BG_STRIDE + kk + 8 + 2*tig];
                    al[mt][0] = *(const unsigned*)&Al[r * BG_STRIDE + kk + 2*tig];
                    al[mt][1] = *(const unsigned*)&Al[(r + 8) * BG_STRIDE + kk + 2*tig];
                    al[mt][2] = *(const unsigned*)&Al[r * BG_STRIDE + kk + 8 + 2*tig];
                    al[mt][3] = *(const unsigned*)&Al[(r + 8) * BG_STRIDE + kk + 8 + 2*tig];
                }
                #pragma unroll
                for (int nt = 0; nt < 8; nt++) {
                    const int rn = n0 + nt * 8 + g;
                    const unsigned bh0 = *(const unsigned*)&Bh[rn * BG_STRIDE + kk + 2*tig];
                    const unsigned bh1 = *(const unsigned*)&Bh[rn * BG_STRIDE + kk + 8 + 2*tig];
                    const unsigned bl0 = *(const unsigned*)&Bl[rn * BG_STRIDE + kk + 2*tig];
                    const unsigned bl1 = *(const unsigned*)&Bl[rn * BG_STRIDE + kk + 8 + 2*tig];
                    #pragma unroll
                    for (int mt = 0; mt < 2; mt++) {
                        mma_bf16(acc[mt][nt], ah[mt], bh0, bh1);
                        mma_bf16(acc[mt][nt], ah[mt], bl0, bl1);
                        mma_bf16(acc[mt][nt], al[mt], bh0, bh1);
                    }
                }
            }
        }

        if (kt + 1 < NT) {
            const int nxt = cur ^ 1;
            __nv_bfloat16* Ah = smb + nxt * 4 * BG_MAT;
            __nv_bfloat16* Al = Ah + BG_MAT;
            __nv_bfloat16* Bh = Ah + 2 * BG_MAT;
            __nv_bfloat16* Bl = Ah + 3 * BG_MAT;
            const float vf[16] = { pv[0].x,pv[0].y,pv[0].z,pv[0].w,
                                   pv[1].x,pv[1].y,pv[1].z,pv[1].w,
                                   pv[2].x,pv[2].y,pv[2].z,pv[2].w,
                                   pv[3].x,pv[3].y,pv[3].z,pv[3].w };
            #pragma unroll
            for (int p = 0; p < 8; p++) {
                __nv_bfloat16 h0, l0, h1, l1;
                bf16_split(vf[2*p],     h0, l0);
                bf16_split(vf[2*p + 1], h1, l1);
                __nv_bfloat162 th; th.x = h0; th.y = h1;
                __nv_bfloat162 tl; tl.x = l0; tl.y = l1;
                *(__nv_bfloat162*)&Ah[ar * BG_STRIDE + akq + 2*p] = th;
                *(__nv_bfloat162*)&Al[ar * BG_STRIDE + akq + 2*p] = tl;
            }
            *(uint4*)&Bh[ar * BG_STRIDE + akq]     = pbh[0];
            *(uint4*)&Bh[ar * BG_STRIDE + akq + 8] = pbh[1];
            *(uint4*)&Bl[ar * BG_STRIDE + akq]     = pbl[0];
            *(uint4*)&Bl[ar * BG_STRIDE + akq + 8] = pbl[1];
            __syncthreads();
            cur = nxt;
        }
    }

    #pragma unroll
    for (int mt = 0; mt < 2; mt++) {
        const long row = bm + m0 + mt * 16 + g;
        #pragma unroll
        for (int nt = 0; nt < 8; nt++) {
            const int col = bn + n0 + nt * 8 + 2 * tig;
            float c0 = acc[mt][nt][0], c1 = acc[mt][nt][1];
            float c2 = acc[mt][nt][2], c3 = acc[mt][nt][3];
            if (BIAS) {
                const float b0 = bias1[col]     + bias2[col];
                const float b1 = bias1[col + 1] + bias2[col + 1];
                c0 += b0; c1 += b1; c2 += b0; c3 += b1;
            }
            *(float2*)&C[row * Nn + col]       = make_float2(c0, c1);
            *(float2*)&C[(row + 8) * Nn + col] = make_float2(c2, c3);
        }
    }
}

// ----------------------------------------------------------------------------
// Shared attention phases, GPG graphs per CTA (R3-proven structure).
// ----------------------------------------------------------------------------
__device__ __forceinline__ void gat_attn_body(
    float* sH, const float* sAs, const float* sAd, const float* sB,
    float* s_as, float* s_ad, float* s_m, float* s_dn, float* s_ev,
    const int* s_src, const int* s_dst, const int* s_cs, const int* s_ce,
    float* outb, long out_base_graph, int relu_flag)
{
    const int tid = threadIdx.x;

    for (int i = tid; i < GPG * 64; i += 256) {
        const int g = i >> 6, t = i & 63;
        if (t < 34) {
            const int n = t >> 1, hh = t & 1;
            const float* hp = &sH[g * GROW + n * 128 + hh * 64];
            float as = 0.f, ad = 0.f;
            #pragma unroll 8
            for (int d = 0; d < 64; d++) {
                as += hp[d] * sAs[hh * 64 + d];
                ad += hp[d] * sAd[hh * 64 + d];
            }
            s_as[g * 34 + t] = as; s_ad[g * 34 + t] = ad;
        }
    }
    __syncthreads();

    for (int i = tid; i < GPG * 256; i += 256) {
        const int g = i >> 8, t = i & 255;
        if (t < 162) {
            const int e = t >> 1, hh = t & 1;
            const float raw = s_as[g * 34 + s_src[e] * 2 + hh]
                            + s_ad[g * 34 + s_dst[e] * 2 + hh];
            s_ev[g * 162 + t] = raw > 0.f ? raw : 0.2f * raw;
        }
    }
    __syncthreads();

    for (int i = tid; i < GPG * 64; i += 256) {
        const int g = i >> 6, t = i & 63;
        if (t < 34) {
            const int n = t >> 1, hh = t & 1;
            float m = -1e30f;
            for (int p = s_cs[n]; p < s_cs[n + 1]; p++)
                m = fmaxf(m, s_ev[g * 162 + s_ce[p] * 2 + hh]);
            float den = 0.f;
            for (int p = s_cs[n]; p < s_cs[n + 1]; p++)
                den += __expf(s_ev[g * 162 + s_ce[p] * 2 + hh] - m);
            s_m[g * 34 + t] = m; s_dn[g * 34 + t] = den;
        }
    }
    __syncthreads();

    for (int i = tid; i < GPG * 256; i += 256) {
        const int g = i >> 8, t = i & 255;
        if (t < 162) {
            const int e = t >> 1, hh = t & 1;
            const int d = s_dst[e];
            s_ev[g * 162 + t] = __expf(s_ev[g * 162 + t] - s_m[g * 34 + d * 2 + hh])
                                / (s_dn[g * 34 + d * 2 + hh] + 1e-16f);
        }
    }
    __syncthreads();

    for (int i = tid; i < GPG * NNODES * 32; i += 256) {
        const int g = i / (NNODES * 32);
        const int r = i - g * (NNODES * 32);
        const int n = r >> 5;
        const int q = (r & 31) << 2;
        const int hh = q >> 6;
        float4 acc = make_float4(0.f, 0.f, 0.f, 0.f);
        for (int p = s_cs[n]; p < s_cs[n + 1]; p++) {
            const int e = s_ce[p];
            const float al = s_ev[g * 162 + e * 2 + hh];
            const float4 hv = *(const float4*)&sH[g * GROW + s_src[e] * 128 + q];
            acc.x += al * hv.x; acc.y += al * hv.y;
            acc.z += al * hv.z; acc.w += al * hv.w;
        }
        const float4 b4 = *(const float4*)&sB[q];
        acc.x += b4.x; acc.y += b4.y; acc.z += b4.z; acc.w += b4.w;
        if (relu_flag) {
            acc.x = fmaxf(acc.x, 0.f); acc.y = fmaxf(acc.y, 0.f);
            acc.z = fmaxf(acc.z, 0.f); acc.w = fmaxf(acc.w, 0.f);
        }
        *(float4*)&outb[(out_base_graph + g) * GROW + n * 128 + q] = acc;
    }
}

// parallel CSR load from precomputed globals (replaces per-CTA serial build)
__device__ __forceinline__ void gat_load_csr(
    int tid, int* s_src, int* s_dst, int* s_cs, int* s_ce)
{
    if (tid < NEDGES) {
        s_src[tid] = g_csr_src[tid];
        s_dst[tid] = g_csr_dst[tid];
        s_ce[tid]  = g_csr_ce[tid];
    }
    if (tid < NNODES + 1) s_cs[tid] = g_csr_cs[tid];
}

// ----------------------------------------------------------------------------
// GAT layer 0, fused projection (CIN=3): H computed in smem directly from x.
// ----------------------------------------------------------------------------
__global__ void __launch_bounds__(256)
gat_attn0(const float* __restrict__ x, const float* __restrict__ W0,
          const float* __restrict__ a_src, const float* __restrict__ a_dst,
          const float* __restrict__ bias,
          int out_sel, int relu_flag)
{
    extern __shared__ __align__(16) float smem[];
    float* sH   = smem;                    // GPG*2176
    float* sW0  = sH  + GPG * GROW;        // 384
    float* sX   = sW0 + 384;               // GPG*17*3
    float* sAs  = (float*)(((unsigned long)(sX + GPG * NNODES * 3) + 15) & ~15UL);
    float* sAd  = sAs + 128;
    float* sB   = sAd + 128;
    float* s_as = sB  + 128;               // GPG*34
    float* s_ad = s_as + GPG * 34;
    float* s_m  = s_ad + GPG * 34;
    float* s_dn = s_m  + GPG * 34;
    float* s_ev = s_dn + GPG * 34;         // GPG*162
    int*   s_src = (int*)(s_ev + GPG * 162);
    int*   s_dst = s_src + NEDGES;
    int*   s_cs  = s_dst + NEDGES;
    int*   s_ce  = s_cs + NNODES + 1;

    const int tid = threadIdx.x;

    gat_load_csr(tid, s_src, s_dst, s_cs, s_ce);
    if (tid < 128) { sAs[tid] = a_src[tid]; sAd[tid] = a_dst[tid]; sB[tid] = bias[tid]; }
    for (int i = tid; i < 384; i += 256) sW0[i] = W0[i];
    const float* xg = x + (long)blockIdx.x * (GPG * NNODES * 3);
    for (int i = tid; i < GPG * NNODES * 3; i += 256) sX[i] = xg[i];
    __syncthreads();

    for (int i = tid; i < GPG * NNODES * 32; i += 256) {
        const int g = i / (NNODES * 32);
        const int r = i - g * (NNODES * 32);
        const int n = r >> 5;
        const int q = (r & 31) << 2;
        const float* xp = &sX[(g * NNODES + n) * 3];
        const float x0 = xp[0], x1 = xp[1], x2 = xp[2];
        const float4 w0 = *(const float4*)&sW0[0 * 128 + q];
        const float4 w1 = *(const float4*)&sW0[1 * 128 + q];
        const float4 w2 = *(const float4*)&sW0[2 * 128 + q];
        float4 o;
        o.x = x0 * w0.x + x1 * w1.x + x2 * w2.x;
        o.y = x0 * w0.y + x1 * w1.y + x2 * w2.y;
        o.z = x0 * w0.z + x1 * w1.z + x2 * w2.z;
        o.w = x0 * w0.w + x1 * w1.w + x2 * w2.w;
        *(float4*)&sH[g * GROW + n * 128 + q] = o;
    }
    __syncthreads();

    gat_attn_body(sH, sAs, sAd, sB, s_as, s_ad, s_m, s_dn, s_ev,
                  s_src, s_dst, s_cs, s_ce,
                  bufsel_w(out_sel), (long)blockIdx.x * GPG, relu_flag);
}

// ----------------------------------------------------------------------------
// GAT attention for layers 1-3 (reads packed g_tmpH).
// ----------------------------------------------------------------------------
__global__ void __launch_bounds__(256)
gat_attn(const float* __restrict__ a_src, const float* __restrict__ a_dst,
         const float* __restrict__ bias,
         int out_sel, int relu_flag)
{
    extern __shared__ __align__(16) float smem[];
    float* sH   = smem;                    // GPG*2176
    float* sAs  = sH  + GPG * GROW;
    float* sAd  = sAs + 128;
    float* sB   = sAd + 128;
    float* s_as = sB  + 128;
    float* s_ad = s_as + GPG * 34;
    float* s_m  = s_ad + GPG * 34;
    float* s_dn = s_m  + GPG * 34;
    float* s_ev = s_dn + GPG * 34;
    int*   s_src = (int*)(s_ev + GPG * 162);
    int*   s_dst = s_src + NEDGES;
    int*   s_cs  = s_dst + NEDGES;
    int*   s_ce  = s_cs + NNODES + 1;

    const int tid = threadIdx.x;

    gat_load_csr(tid, s_src, s_dst, s_cs, s_ce);
    if (tid < 128) { sAs[tid] = a_src[tid]; sAd[tid] = a_dst[tid]; sB[tid] = bias[tid]; }

    const float* Hsrc = g_tmpH + (long)blockIdx.x * (GPG * GROW);
    for (int i = tid; i < (GPG * GROW) / 4; i += 256)
        *(float4*)&sH[i * 4] = *(const float4*)&Hsrc[i * 4];
    __syncthreads();

    gat_attn_body(sH, sAs, sAd, sB, s_as, s_ad, s_m, s_dn, s_ev,
                  s_src, s_dst, s_cs, s_ce,
                  bufsel_w(out_sel), (long)blockIdx.x * GPG, relu_flag);
}

// ----------------------------------------------------------------------------
// LSTM recurrence: 32 clusters x 4 CTAs (grid (32,4), cluster (1,4)).
// h exchanged via DSMEM; one cluster.sync per step (double-buffered sOut).
// ----------------------------------------------------------------------------
__global__ void __cluster_dims__(1, 4, 1) lstm_recur(const float* __restrict__ whh, int out_sel)
{
    extern __shared__ __align__(16) float smem[];
    float* sW   = smem;                 // 128*132
    float* sH   = sW + 128 * 132;       // 8*128
    float* sC   = sH + 8 * 128;         // 8*32
    float* sPre = sC + 8 * 32;          // 8*128
    float* sOut = sPre + 8 * 128;       // 2 * 8*32

    float* hseq = (out_sel == 0) ? g_h1 : g_h2;
    const float* pre = g_pre;

    cg::cluster_group cluster = cg::this_cluster();

    const int tid = threadIdx.x;
    const int b0 = blockIdx.x * 8;
    const int myrank = blockIdx.y;
    const int d0 = myrank * 32;

    const int j    = tid & 127;
    const int half = tid >> 7;
    const int gidx = ((j >> 5) << 7) + d0 + (j & 31);

    float* peerOut[4];
    #pragma unroll
    for (int r = 0; r < 4; r++)
        peerOut[r] = cluster.map_shared_rank(sOut, r);

    for (int i = tid; i < 128 * 128; i += blockDim.x) {
        const int r = i >> 7, k = i & 127;
        const int jr = ((r >> 5) << 7) + d0 + (r & 31);
        sW[r * 132 + k] = whh[jr * 128 + k];
    }
    for (int i = tid; i < 8 * 128; i += blockDim.x) sH[i] = 0.f;
    {
        const int row = tid >> 5, l = tid & 31;
        sC[row * 32 + l] = 0.f;
    }
    __syncthreads();
    cluster.sync();

    int parity = 0;
    for (int t = 0; t < SEQ; t++) {
        {
            const long pb = ((long)(b0 + half * 4) * SEQ + t) * GATES + gidx;
            const long rs = (long)SEQ * GATES;
            float a0 = pre[pb];
            float a1 = pre[pb + rs];
            float a2 = pre[pb + 2 * rs];
            float a3 = pre[pb + 3 * rs];
            const float4* w4 = (const float4*)&sW[j * 132];
            const float4* h0 = (const float4*)&sH[(half * 4 + 0) * 128];
            const float4* h1 = (const float4*)&sH[(half * 4 + 1) * 128];
            const float4* h2 = (const float4*)&sH[(half * 4 + 2) * 128];
            const float4* h3 = (const float4*)&sH[(half * 4 + 3) * 128];
            #pragma unroll 8
            for (int k4 = 0; k4 < 32; k4++) {
                const float4 w = w4[k4];
                const float4 v0 = h0[k4];
                const float4 v1 = h1[k4];
                const float4 v2 = h2[k4];
                const float4 v3 = h3[k4];
                a0 += w.x * v0.x + w.y * v0.y + w.z * v0.z + w.w * v0.w;
                a1 += w.x * v1.x + w.y * v1.y + w.z * v1.z + w.w * v1.w;
                a2 += w.x * v2.x + w.y * v2.y + w.z * v2.z + w.w * v2.w;
                a3 += w.x * v3.x + w.y * v3.y + w.z * v3.z + w.w * v3.w;
            }
            sPre[(half * 4 + 0) * 128 + j] = a0;
            sPre[(half * 4 + 1) * 128 + j] = a1;
            sPre[(half * 4 + 2) * 128 + j] = a2;
            sPre[(half * 4 + 3) * 128 + j] = a3;
        }
        __syncthreads();

        {
            const int row = tid >> 5, l = tid & 31;
            const float a0 = sPre[row * 128 + l];
            const float a1 = sPre[row * 128 + 32 + l];
            const float a2 = sPre[row * 128 + 64 + l];
            const float a3 = sPre[row * 128 + 96 + l];
            const float ig = 1.f / (1.f + expf(-a0));
            const float fg = 1.f / (1.f + expf(-a1));
            const float gg = tanhf(a2);
            const float og = 1.f / (1.f + expf(-a3));
            const float c = fg * sC[row * 32 + l] + ig * gg;
            sC[row * 32 + l] = c;
            const float h = og * tanhf(c);
            sOut[parity * 256 + row * 32 + l] = h;
            hseq[((long)(b0 + row) * SEQ + t) * 128 + d0 + l] = h;
        }

        cluster.sync();
        for (int i = tid; i < 8 * 128; i += blockDim.x) {
            const int row = i >> 7, k = i & 127;
            const int srck = k >> 5, l = k & 31;
            sH[i] = peerOut[srck][parity * 256 + row * 32 + l];
        }
        __syncthreads();
        parity ^= 1;
    }
}

// ----------------------------------------------------------------------------
// Temporal attention + FC head. One CTA (128 threads) per batch row.
// ----------------------------------------------------------------------------
__global__ void attn_fc(const float* __restrict__ attn_w, const float* __restrict__ attn_b,
                        const float* __restrict__ fc_w,   const float* __restrict__ fc_b,
                        float* __restrict__ out)
{
    __shared__ float sw[128];
    __shared__ float sc[SEQ];
    __shared__ float sctx[128];

    const int b = blockIdx.x, tid = threadIdx.x;
    const float* h2 = g_h2 + (long)b * SEQ * 128;

    sw[tid] = attn_w[tid];
    __syncthreads();

    if (tid < SEQ) {
        const float* hp = h2 + tid * 128;
        float acc = attn_b[0];
        #pragma unroll 8
        for (int k = 0; k < 128; k++) acc += hp[k] * sw[k];
        sc[tid] = tanhf(acc);
    }
    __syncthreads();

    if (tid == 0) {
        float m = -1e30f;
        for (int t = 0; t < SEQ; t++) m = fmaxf(m, sc[t]);
        float s = 0.f;
        for (int t = 0; t < SEQ; t++) { sc[t] = __expf(sc[t] - m); s += sc[t]; }
        const float inv = 1.f / s;
        for (int t = 0; t < SEQ; t++) sc[t] *= inv;
    }
    __syncthreads();

    {
        float acc = 0.f;
        for (int t = 0; t < SEQ; t++) acc += sc[t] * h2[t * 128 + tid];
        sctx[tid] = acc;
    }
    __syncthreads();

    if (tid < 10) {
        float acc = fc_b[tid];
        #pragma unroll 8
        for (int k = 0; k < 128; k++) acc += sctx[k] * fc_w[tid * 128 + k];
        out[b * 10 + tid] = acc;
    }
}

// ----------------------------------------------------------------------------
// Launcher
// ----------------------------------------------------------------------------
extern "C" void kernel_launch(void* const* d_in, const int* in_sizes, int n_in,
                              void* d_out, int out_size)
{
    const float* x    = (const float*)d_in[0];
    const int*   eidx = (const int*)  d_in[1];
    const float* gw[4]  = { (const float*)d_in[2],  (const float*)d_in[6],
                            (const float*)d_in[10], (const float*)d_in[14] };
    const float* gas[4] = { (const float*)d_in[3],  (const float*)d_in[7],
                            (const float*)d_in[11], (const float*)d_in[15] };
    const float* gad[4] = { (const float*)d_in[4],  (const float*)d_in[8],
                            (const float*)d_in[12], (const float*)d_in[16] };
    const float* gb[4]  = { (const float*)d_in[5],  (const float*)d_in[9],
                            (const float*)d_in[13], (const float*)d_in[17] };
    const float* wih0 = (const float*)d_in[18];
    const float* whh0 = (const float*)d_in[19];
    const float* bih0 = (const float*)d_in[20];
    const float* bhh0 = (const float*)d_in[21];
    const float* wih1 = (const float*)d_in[22];
    const float* whh1 = (const float*)d_in[23];
    const float* bih1 = (const float*)d_in[24];
    const float* bhh1 = (const float*)d_in[25];
    const float* attn_w = (const float*)d_in[26];
    const float* attn_b = (const float*)d_in[27];
    const float* fc_w   = (const float*)d_in[28];
    const float* fc_b   = (const float*)d_in[29];
    float* out = (float*)d_out;

    const int smem_attn  = ((GPG * GROW + 3 * 128 + 4 * (GPG * 34) + GPG * 162) +
                            (NEDGES * 3 + NNODES + 1 + 8)) * 4;
    const int smem_attn0 = smem_attn + (384 + GPG * NNODES * 3 + 8) * 4;
    const int smem_rec   = (128 * 132 + 8 * 128 + 8 * 32 + 8 * 128 + 2 * 8 * 32) * 4;
    const int smem_bg    = 2 * 4 * BG_MAT * 2;   // 81920

    cudaFuncSetAttribute((const void*)gat_attn,
                         cudaFuncAttributeMaxDynamicSharedMemorySize, smem_attn);
    cudaFuncSetAttribute((const void*)gat_attn0,
                         cudaFuncAttributeMaxDynamicSharedMemorySize, smem_attn0);
    cudaFuncSetAttribute((const void*)lstm_recur,
                         cudaFuncAttributeMaxDynamicSharedMemorySize, smem_rec);
    cudaFuncSetAttribute((const void*)bgemm<false, false>,
                         cudaFuncAttributeMaxDynamicSharedMemorySize, smem_bg);
    cudaFuncSetAttribute((const void*)bgemm<true, true>,
                         cudaFuncAttributeMaxDynamicSharedMemorySize, smem_bg);

    const int attn_grid = NG / GPG;      // 4096
    const int mm_grid   = MROWS / 128;   // 2176

    // prep: CSR + bf16 hi/lo weights
    prep_csr<<<1, 128>>>(eidx);
    prep_tn  <<<(GATES * LSTM_IN + 255) / 256, 256>>>(wih0, 0, GATES * LSTM_IN);
    prep_tn  <<<(GATES * HDIM    + 255) / 256, 256>>>(wih1, 1, GATES * HDIM);
    prep_nn_t<<<(HDIM * HDIM     + 255) / 256, 256>>>(gw[1], 2, HDIM, HDIM);
    prep_nn_t<<<(HDIM * HDIM     + 255) / 256, 256>>>(gw[2], 3, HDIM, HDIM);
    prep_nn_t<<<(HDIM * HDIM     + 255) / 256, 256>>>(gw[3], 4, HDIM, HDIM);

    // ---- GAT layer 0 (fused projection): x -> bufA (relu)
    gat_attn0<<<attn_grid, 256, smem_attn0>>>(x, gw[0], gas[0], gad[0], gb[0], 0, 1);

    // ---- GAT layer 1: bufA @ W1 -> tmpH -> attn -> bufB
    bgemm<false, false><<<dim3(mm_grid, 1), 256, smem_bg>>>(0, 2, nullptr, nullptr, 2, MROWS, 128, 128);
    gat_attn<<<attn_grid, 256, smem_attn>>>(gas[1], gad[1], gb[1], 1, 0);

    // ---- GAT layer 2: bufB @ W2 -> tmpH -> attn -> bufA (relu)
    bgemm<false, false><<<dim3(mm_grid, 1), 256, smem_bg>>>(1, 3, nullptr, nullptr, 2, MROWS, 128, 128);
    gat_attn<<<attn_grid, 256, smem_attn>>>(gas[2], gad[2], gb[2], 0, 1);

    // ---- GAT layer 3: bufA @ W3 -> tmpH -> attn -> bufB
    bgemm<false, false><<<dim3(mm_grid, 1), 256, smem_bg>>>(0, 4, nullptr, nullptr, 2, MROWS, 128, 128);
    gat_attn<<<attn_grid, 256, smem_attn>>>(gas[3], gad[3], gb[3], 1, 0);

    // ---- LSTM layer 0: pre-gates GEMM (SWAP grid) + recurrence
    bgemm<true, true><<<dim3(GATES / 128, NG / 128), 256, smem_bg>>>(1, 0, bih0, bhh0, 4, NG, GATES, LSTM_IN);
    lstm_recur<<<dim3(32, 4), 256, smem_rec>>>(whh0, 0);

    // ---- LSTM layer 1: pre-gates GEMM (SWAP grid) + recurrence
    bgemm<true, true><<<dim3(GATES / 128, NG / 128), 256, smem_bg>>>(3, 1, bih1, bhh1, 4, NG, GATES, HDIM);
    lstm_recur<<<dim3(32, 4), 256, smem_rec>>>(whh1, 1);

    // ---- head
    attn_fc<<<BATCH, 128>>>(attn_w, attn_b, fc_w, fc_b, out);
}